// round 16
// baseline (speedup 1.0000x reference)
#include <cuda_runtime.h>

// S2Conv v9: single fused persistent kernel.
// Phase 1: branchless batched conv (v7 core) -> store raw + per-channel stats.
// Grid barrier (512 blocks, 4 CTAs/SM guaranteed by launch_bounds).
// Phase 2: per-block finalize (smem scale/bias) + in-place normalize+relu of
// exactly the tiles this block wrote (L2-hot). Self-cleaning stats for graph
// replay (last block re-zeroes accumulators and barrier counter).
// N=64, C=128, T=2048, S=9.

#define Nn 64
#define Cc 128
#define Tt 2048
#define Ss 9
#define CG 32          // output channels per tile (8 warps x 4)
#define TBLK 128       // t per tile (4 segments x 32 per warp)
#define NBLK 512
#define TPB 8          // tiles per block (4096 tiles total)

__device__ float g_sum[Cc];      // zero at module load; re-zeroed each run
__device__ float g_sumsq[Cc];
__device__ unsigned g_arrive;    // zero at module load; self-resetting
__constant__ float c_w[Cc * Ss];

// acc[cl][s] += w[cb+cl, r-cl] * xs[cb-4+r, tbase + 32s], r = 0..11.
// tbase includes this thread's lane. xs[cc,t] = x[cc, t+4-cc%9], zero-padded.
// CEDGE / TEDGE: clamp + SEL instead of branches.
template<bool CEDGE, bool TEDGE>
__device__ __forceinline__ void conv_core(
    const float* __restrict__ xn, int cb, int tbase, float (&acc)[4][4])
{
    #pragma unroll
    for (int wv = 0; wv < 3; wv++) {               // 3 waves of 4 rows
        float v[4][4];
        #pragma unroll
        for (int i = 0; i < 4; i++) {              // 16 batched LDGs
            const int r  = wv * 4 + i;
            const int cc = cb - 4 + r;
            const int ccl = CEDGE ? min(max(cc, 0), Cc - 1) : cc;
            const int off = 4 - (ccl % 9);
            const float* xr = xn + (size_t)ccl * Tt + tbase + off;
            #pragma unroll
            for (int s = 0; s < 4; s++) {
                float t;
                if (TEDGE) {
                    const int ts  = tbase + s * 32 + off;
                    const int tsc = min(max(ts, 0), Tt - 1);
                    t = __ldg(xn + (size_t)ccl * Tt + tsc);
                    t = ((unsigned)ts < (unsigned)Tt) ? t : 0.0f;
                } else {
                    t = __ldg(&xr[s * 32]);
                }
                if (CEDGE) t = ((unsigned)cc < (unsigned)Cc) ? t : 0.0f;
                v[i][s] = t;
            }
        }
        #pragma unroll
        for (int i = 0; i < 4; i++) {
            const int r = wv * 4 + i;
            #pragma unroll
            for (int cl = 0; cl < 4; cl++) {
                if (cl >= r - 8 && cl <= r) {
                    const float wt = c_w[(cb + cl) * Ss + (r - cl)];
                    #pragma unroll
                    for (int s = 0; s < 4; s++)
                        acc[cl][s] = fmaf(wt, v[i][s], acc[cl][s]);
                }
            }
        }
    }
}

__global__ __launch_bounds__(256, 4) void fused_kernel(
    const float* __restrict__ x,
    const float* __restrict__ gamma,
    const float* __restrict__ beta,
    float* __restrict__ out)
{
    __shared__ float s_scale[CG], s_bias[CG];

    const int tid  = threadIdx.x;
    const int lane = tid & 31;
    const int wid  = tid >> 5;

    // Tiles bid*8 .. bid*8+7 share the same by (channel group) and n:
    // (bid*8) % 16 in {0,8}, so tile>>4 is constant across the 8 tiles.
    const int tile0 = blockIdx.x * TPB;
    const int by    = (tile0 >> 4) & 3;
    const int n     = tile0 >> 6;
    const int cb    = by * CG + wid * 4;
    const float* xn = x + (size_t)n * Cc * Tt;
    const bool cedge = (by == 0) || (by == 3);

    // ================= Phase 1: conv + store raw + stats =================
    #pragma unroll 1
    for (int k = 0; k < TPB; k++) {
        const int bx    = (tile0 + k) & 15;
        const int tbase = bx * TBLK + lane;

        float acc[4][4];
        #pragma unroll
        for (int cl = 0; cl < 4; cl++)
            #pragma unroll
            for (int s = 0; s < 4; s++) acc[cl][s] = 0.f;

        const bool tedge = (bx == 0) || (bx == 15);
        if      ( cedge &&  tedge) conv_core<true , true >(xn, cb, tbase, acc);
        else if ( cedge && !tedge) conv_core<true , false>(xn, cb, tbase, acc);
        else if (!cedge &&  tedge) conv_core<false, true >(xn, cb, tbase, acc);
        else                       conv_core<false, false>(xn, cb, tbase, acc);

        // Store raw conv (coalesced scalar STG).
        #pragma unroll
        for (int cl = 0; cl < 4; cl++) {
            float* orow = out + ((size_t)n * Cc + cb + cl) * Tt + tbase;
            #pragma unroll
            for (int s = 0; s < 4; s++)
                orow[s * 32] = acc[cl][s];
        }

        // Stats: local -> warp shuffle -> global atomic.
        #pragma unroll
        for (int cl = 0; cl < 4; cl++) {
            float s1 = (acc[cl][0] + acc[cl][1]) + (acc[cl][2] + acc[cl][3]);
            float s2 = fmaf(acc[cl][0], acc[cl][0], fmaf(acc[cl][1], acc[cl][1],
                       fmaf(acc[cl][2], acc[cl][2], acc[cl][3] * acc[cl][3])));
            #pragma unroll
            for (int o = 16; o > 0; o >>= 1) {
                s1 += __shfl_down_sync(0xffffffffu, s1, o);
                s2 += __shfl_down_sync(0xffffffffu, s2, o);
            }
            if (lane == 0) {
                atomicAdd(&g_sum[cb + cl],   s1);
                atomicAdd(&g_sumsq[cb + cl], s2);
            }
        }
    }

    // ================= Grid barrier =================
    __syncthreads();
    if (tid == 0) {
        __threadfence();
        atomicAdd(&g_arrive, 1u);
        while (*(volatile unsigned*)&g_arrive < NBLK) { }
    }
    __syncthreads();
    __threadfence();

    // ================= Finalize (once per block; channels fixed) =========
    if (tid < CG) {
        const int c = by * CG + tid;
        const float s1 = __ldcg(&g_sum[c]);
        const float s2 = __ldcg(&g_sumsq[c]);
        const float inv = 1.0f / ((float)Nn * (float)Tt);
        const float mean = s1 * inv;
        const float var  = s2 * inv - mean * mean;
        const float rstd = rsqrtf(var + 1e-5f);
        const float sc   = gamma[c] * rstd;
        s_scale[tid] = sc;
        s_bias[tid]  = beta[c] - mean * sc;
    }
    __syncthreads();

    // ================= Phase 2: in-place normalize + relu (L2-hot) =======
    #pragma unroll 1
    for (int k = 0; k < TPB; k++) {
        const int bx = (tile0 + k) & 15;
        float* base = out + ((size_t)n * Cc + by * CG) * Tt + bx * TBLK;
        #pragma unroll
        for (int j = 0; j < 4; j++) {            // 1024 float4 per tile
            const int idx = tid + j * 256;
            const int ch  = idx >> 5;            // 32 float4 per channel row
            const int col = (idx & 31) * 4;
            float4* p = reinterpret_cast<float4*>(base + (size_t)ch * Tt + col);
            float4 v = *p;
            const float sc = s_scale[ch];
            const float bs = s_bias[ch];
            v.x = fmaxf(fmaf(v.x, sc, bs), 0.0f);
            v.y = fmaxf(fmaf(v.y, sc, bs), 0.0f);
            v.z = fmaxf(fmaf(v.z, sc, bs), 0.0f);
            v.w = fmaxf(fmaf(v.w, sc, bs), 0.0f);
            *p = v;
        }
    }

    // ================= Cleanup for next graph replay =================
    __syncthreads();
    if (tid == 0) {
        __threadfence();
        const unsigned v = atomicAdd(&g_arrive, 1u);
        if (v == 2u * NBLK - 1u) {               // last block overall
            for (int i = 0; i < Cc; i++) { g_sum[i] = 0.f; g_sumsq[i] = 0.f; }
            __threadfence();
            g_arrive = 0u;
        }
    }
}

extern "C" void kernel_launch(void* const* d_in, const int* in_sizes, int n_in,
                              void* d_out, int out_size)
{
    const float* x     = (const float*)d_in[0];
    const float* w     = (const float*)d_in[1];
    const float* gamma = (const float*)d_in[2];
    const float* beta  = (const float*)d_in[3];
    float* out = (float*)d_out;

    cudaMemcpyToSymbolAsync(c_w, w, Cc * Ss * sizeof(float), 0,
                            cudaMemcpyDeviceToDevice, 0);
    fused_kernel<<<NBLK, 256>>>(x, gamma, beta, out);
}

// round 17
// speedup vs baseline: 1.2631x; 1.2631x over previous
#include <cuda_runtime.h>

// S2Conv v10: v8 two-kernel structure (best so far), with the conv core's
// load batch widened to 2 waves of 6 rows (24 in-flight LDGs) to cut exposed
// DRAM latency on the cold x read.
// Pass 1: conv + store raw + per-channel stats. Finalize. Pass 2: norm+relu.
// N=64, C=128, T=2048, S=9.

#define Nn 64
#define Cc 128
#define Tt 2048
#define Ss 9
#define CG 32          // output channels per block (8 warps x 4)
#define TBLK 128       // t per warp (4 segments x 32)

__device__ float g_sum[Cc];
__device__ float g_sumsq[Cc];
__device__ float g_scale[Cc];
__device__ float g_bias[Cc];
__constant__ float c_w[Cc * Ss];

__global__ void init_kernel() {
    int i = threadIdx.x;
    if (i < Cc) { g_sum[i] = 0.0f; g_sumsq[i] = 0.0f; }
}

// acc[cl][s] += w[cb+cl, r-cl] * xs[cb-4+r, tbase + 32s], r = 0..11.
// tbase includes this thread's lane. xs[cc,t] = x[cc, t+4-cc%9], zero-padded.
// CEDGE / TEDGE: clamp + SEL instead of branches.
// 2 waves x 6 rows: 24 batched LDGs per wave.
template<bool CEDGE, bool TEDGE>
__device__ __forceinline__ void conv_core(
    const float* __restrict__ xn, int cb, int tbase, float (&acc)[4][4])
{
    #pragma unroll
    for (int wv = 0; wv < 2; wv++) {               // 2 waves of 6 rows
        float v[6][4];
        // ---- batched loads: 24 LDGs, no branches
        #pragma unroll
        for (int i = 0; i < 6; i++) {
            const int r  = wv * 6 + i;
            const int cc = cb - 4 + r;
            const int ccl = CEDGE ? min(max(cc, 0), Cc - 1) : cc;
            const int off = 4 - (ccl % 9);
            const float* xr = xn + (size_t)ccl * Tt + tbase + off;
            #pragma unroll
            for (int s = 0; s < 4; s++) {
                float t;
                if (TEDGE) {
                    const int ts  = tbase + s * 32 + off;      // per-lane global t
                    const int tsc = min(max(ts, 0), Tt - 1);
                    t = __ldg(xn + (size_t)ccl * Tt + tsc);
                    t = ((unsigned)ts < (unsigned)Tt) ? t : 0.0f;
                } else {
                    t = __ldg(&xr[s * 32]);
                }
                if (CEDGE) t = ((unsigned)cc < (unsigned)Cc) ? t : 0.0f;
                v[i][s] = t;
            }
        }
        // ---- FMAs on the wave
        #pragma unroll
        for (int i = 0; i < 6; i++) {
            const int r = wv * 6 + i;
            #pragma unroll
            for (int cl = 0; cl < 4; cl++) {
                if (cl >= r - 8 && cl <= r) {
                    const float wt = c_w[(cb + cl) * Ss + (r - cl)];   // warp-uniform
                    #pragma unroll
                    for (int s = 0; s < 4; s++)
                        acc[cl][s] = fmaf(wt, v[i][s], acc[cl][s]);
                }
            }
        }
    }
}

// ---- Pass 1: conv + store raw + per-channel stats.
__global__ __launch_bounds__(256, 4) void conv_stats_kernel(
    const float* __restrict__ x, float* __restrict__ out)
{
    const int lane = threadIdx.x & 31;
    const int wid  = threadIdx.x >> 5;
    const int cb   = blockIdx.y * CG + wid * 4;
    const int n    = blockIdx.z;
    const int tbase = blockIdx.x * TBLK + lane;     // lane folded in
    const float* xn = x + (size_t)n * Cc * Tt;

    float acc[4][4];
    #pragma unroll
    for (int cl = 0; cl < 4; cl++)
        #pragma unroll
        for (int s = 0; s < 4; s++) acc[cl][s] = 0.f;

    const bool tedge = (blockIdx.x == 0) || (blockIdx.x == Tt / TBLK - 1);
    const bool cedge = (blockIdx.y == 0) || (blockIdx.y == Cc / CG - 1);
    if      ( cedge &&  tedge) conv_core<true , true >(xn, cb, tbase, acc);
    else if ( cedge && !tedge) conv_core<true , false>(xn, cb, tbase, acc);
    else if (!cedge &&  tedge) conv_core<false, true >(xn, cb, tbase, acc);
    else                       conv_core<false, false>(xn, cb, tbase, acc);

    // Store raw conv output (coalesced scalar STG).
    #pragma unroll
    for (int cl = 0; cl < 4; cl++) {
        float* orow = out + ((size_t)n * Cc + cb + cl) * Tt + tbase;
        #pragma unroll
        for (int s = 0; s < 4; s++)
            orow[s * 32] = acc[cl][s];
    }

    // Per-channel stats: local -> warp shuffle -> global atomic.
    #pragma unroll
    for (int cl = 0; cl < 4; cl++) {
        float s1 = (acc[cl][0] + acc[cl][1]) + (acc[cl][2] + acc[cl][3]);
        float s2 = fmaf(acc[cl][0], acc[cl][0], fmaf(acc[cl][1], acc[cl][1],
                   fmaf(acc[cl][2], acc[cl][2], acc[cl][3] * acc[cl][3])));
        #pragma unroll
        for (int o = 16; o > 0; o >>= 1) {
            s1 += __shfl_down_sync(0xffffffffu, s1, o);
            s2 += __shfl_down_sync(0xffffffffu, s2, o);
        }
        if (lane == 0) {
            atomicAdd(&g_sum[cb + cl],   s1);
            atomicAdd(&g_sumsq[cb + cl], s2);
        }
    }
}

// ---- Finalize: per-channel scale/bias.
__global__ void finalize_kernel(const float* __restrict__ gamma,
                                const float* __restrict__ beta)
{
    int c = threadIdx.x;
    if (c >= Cc) return;
    const float inv = 1.0f / ((float)Nn * (float)Tt);
    float mean = g_sum[c] * inv;
    float var  = g_sumsq[c] * inv - mean * mean;
    float rstd = rsqrtf(var + 1e-5f);
    float sc   = gamma[c] * rstd;
    g_scale[c] = sc;
    g_bias[c]  = beta[c] - mean * sc;
}

// ---- Pass 2: in-place normalize + relu (out is L2-resident). One block/row.
__global__ __launch_bounds__(256) void norm_kernel(float* __restrict__ out)
{
    const int row = blockIdx.x;          // n*C + c
    const int c   = row & (Cc - 1);
    const float sc = g_scale[c];
    const float b  = g_bias[c];
    float4* p = reinterpret_cast<float4*>(out + (size_t)row * Tt);
    const int tid = threadIdx.x;
    #pragma unroll
    for (int k = 0; k < (Tt / 4) / 256; k++) {
        float4 v = p[tid + k * 256];
        v.x = fmaxf(fmaf(v.x, sc, b), 0.0f);
        v.y = fmaxf(fmaf(v.y, sc, b), 0.0f);
        v.z = fmaxf(fmaf(v.z, sc, b), 0.0f);
        v.w = fmaxf(fmaf(v.w, sc, b), 0.0f);
        p[tid + k * 256] = v;
    }
}

extern "C" void kernel_launch(void* const* d_in, const int* in_sizes, int n_in,
                              void* d_out, int out_size)
{
    const float* x     = (const float*)d_in[0];
    const float* w     = (const float*)d_in[1];
    const float* gamma = (const float*)d_in[2];
    const float* beta  = (const float*)d_in[3];
    float* out = (float*)d_out;

    cudaMemcpyToSymbolAsync(c_w, w, Cc * Ss * sizeof(float), 0,
                            cudaMemcpyDeviceToDevice, 0);

    const dim3 grid(Tt / TBLK, Cc / CG, Nn);   // 16 x 4 x 64 = 4096 blocks
    init_kernel<<<1, 128>>>();
    conv_stats_kernel<<<grid, 256>>>(x, out);
    finalize_kernel<<<1, 128>>>(gamma, beta);
    norm_kernel<<<Nn * Cc, 256>>>(out);
}